// round 1
// baseline (speedup 1.0000x reference)
#include <cuda_runtime.h>
#include <math_constants.h>

// ZBLRepulsion: E = sum over edges of 0.5*Zi*Zj/dr * f(dist) * cos_cutoff(dr)
// Two-pass: pass1 gathers + d2<36 filter + warp compaction; pass2 transcendental math.

#define N_ATOMS_MAX 100032
#define E_MAX 6400000

// Scratch (static __device__ allocations; no cudaMalloc allowed)
__device__ float4 g_P[N_ATOMS_MAX];     // packed {x, y, z, Z_as_int_bits}
__device__ float  g_pow[64];            // z^a_exp lookup
__device__ int    g_count;
__device__ double g_acc;
__device__ int2   g_edges[E_MAX];       // {d2 bits, zi | zj<<8}

// ---------------------------------------------------------------------------
__global__ void prep_kernel(const float* __restrict__ R,
                            const int* __restrict__ Z,
                            const float* __restrict__ a_exp,
                            int n_atoms) {
    int tid = blockIdx.x * blockDim.x + threadIdx.x;
    if (tid < 64) g_pow[tid] = powf((float)tid, a_exp[0]);
    if (tid == 0) { g_count = 0; g_acc = 0.0; }
    int stride = gridDim.x * blockDim.x;
    for (int i = tid; i < n_atoms; i += stride) {
        float4 p;
        p.x = R[3 * i + 0];
        p.y = R[3 * i + 1];
        p.z = R[3 * i + 2];
        p.w = __int_as_float(Z[i]);
        g_P[i] = p;
    }
}

// ---------------------------------------------------------------------------
// Pass 1: 4 edges per thread (int4 index loads), d2 test, warp-aggregated compaction.
__global__ void __launch_bounds__(256)
pass1_kernel(const int* __restrict__ idx, int n_edges, int n_atoms) {
    int t  = blockIdx.x * blockDim.x + threadIdx.x;
    int e0 = t * 4;
    int lane = threadIdx.x & 31;

    int4 ii = make_int4(-1, -1, -1, -1);
    int4 jj = make_int4(-1, -1, -1, -1);
    if (e0 + 3 < n_edges) {
        ii = *reinterpret_cast<const int4*>(idx + e0);
        jj = *reinterpret_cast<const int4*>(idx + n_edges + e0);
    } else if (e0 < n_edges) {
        const int* pi = idx + e0;
        const int* pj = idx + n_edges + e0;
        int rem = n_edges - e0;
        if (rem > 0) { ii.x = pi[0]; jj.x = pj[0]; }
        if (rem > 1) { ii.y = pi[1]; jj.y = pj[1]; }
        if (rem > 2) { ii.z = pi[2]; jj.z = pj[2]; }
    }
    int is[4] = {ii.x, ii.y, ii.z, ii.w};
    int js[4] = {jj.x, jj.y, jj.z, jj.w};

    float d2v[4];
    int   zzv[4];
    bool  pr[4];
#pragma unroll
    for (int k = 0; k < 4; k++) {
        int i = is[k], j = js[k];
        bool valid = ((unsigned)i < (unsigned)n_atoms) & ((unsigned)j < (unsigned)n_atoms);
        float d2 = 1e30f;
        int zz = 0;
        if (valid) {
            float4 pi = g_P[i];
            float4 pj = g_P[j];
            float dx = pj.x - pi.x;
            float dy = pj.y - pi.y;
            float dz = pj.z - pi.z;
            d2 = fmaf(dx, dx, fmaf(dy, dy, dz * dz));
            zz = __float_as_int(pi.w) | (__float_as_int(pj.w) << 8);
        }
        d2v[k] = d2;
        zzv[k] = zz;
        pr[k]  = valid && (d2 < 36.0f);
    }

#pragma unroll
    for (int k = 0; k < 4; k++) {
        unsigned mask = __ballot_sync(0xffffffffu, pr[k]);
        if (mask) {
            int leader = __ffs(mask) - 1;
            int base = 0;
            if (lane == leader) base = atomicAdd(&g_count, __popc(mask));
            base = __shfl_sync(0xffffffffu, base, leader);
            if (pr[k]) {
                int off = base + __popc(mask & ((1u << lane) - 1u));
                g_edges[off] = make_int2(__float_as_int(d2v[k]), zzv[k]);
            }
        }
    }
}

// ---------------------------------------------------------------------------
// Pass 2: transcendental math on compacted edges, hierarchical reduction.
__global__ void __launch_bounds__(256)
pass2_kernel(const float* __restrict__ a_num,
             const float* __restrict__ coef,
             const float* __restrict__ expo) {
    __shared__ float s_pow[64];
    __shared__ float s_red[8];
    if (threadIdx.x < 64) s_pow[threadIdx.x] = g_pow[threadIdx.x];
    __syncthreads();

    int n = g_count;
    float inv_anum = 1.0f / a_num[0];
    float c0 = coef[0], c1 = coef[1], c2 = coef[2], c3 = coef[3];
    float x0 = expo[0], x1 = expo[1], x2 = expo[2], x3 = expo[3];

    float acc = 0.0f;
    int stride = gridDim.x * blockDim.x;
    for (int e = blockIdx.x * blockDim.x + threadIdx.x; e < n; e += stride) {
        int2 ed = g_edges[e];
        float d2 = __int_as_float(ed.x);
        int zi = ed.y & 0xff;
        int zj = (ed.y >> 8) & 0xff;
        float dr = sqrtf(d2);
        dr = fmaxf(dr, 0.02f);                       // lower clip (upper guaranteed by d2<36)
        float cut = 0.5f * (__cosf((CUDART_PI_F / 6.0f) * dr) + 1.0f);
        float dist = dr * (s_pow[zi] + s_pow[zj]) * inv_anum;
        float f = c0 * __expf(-x0 * dist)
                + c1 * __expf(-x1 * dist)
                + c2 * __expf(-x2 * dist)
                + c3 * __expf(-x3 * dist);
        acc += 0.5f * (float)(zi * zj) * f * cut / dr;
    }

    // warp reduce
#pragma unroll
    for (int o = 16; o > 0; o >>= 1)
        acc += __shfl_down_sync(0xffffffffu, acc, o);
    int wid = threadIdx.x >> 5;
    if ((threadIdx.x & 31) == 0) s_red[wid] = acc;
    __syncthreads();
    if (threadIdx.x < 8) {
        float v = s_red[threadIdx.x];
#pragma unroll
        for (int o = 4; o > 0; o >>= 1)
            v += __shfl_down_sync(0xffu, v, o);
        if (threadIdx.x == 0 && v != 0.0f) atomicAdd(&g_acc, (double)v);
    }
}

// ---------------------------------------------------------------------------
__global__ void finalize_kernel(float* __restrict__ out) {
    if (threadIdx.x == 0) out[0] = (float)g_acc;
}

// ---------------------------------------------------------------------------
extern "C" void kernel_launch(void* const* d_in, const int* in_sizes, int n_in,
                              void* d_out, int out_size) {
    const float* R      = (const float*)d_in[0];
    const int*   Z      = (const int*)d_in[1];
    const int*   idx    = (const int*)d_in[2];
    const float* a_exp  = (const float*)d_in[3];
    const float* a_num  = (const float*)d_in[4];
    const float* coef   = (const float*)d_in[5];
    const float* expo   = (const float*)d_in[6];
    float* out = (float*)d_out;

    int n_atoms = in_sizes[1];
    if (n_atoms > N_ATOMS_MAX) n_atoms = N_ATOMS_MAX;
    int n_edges = in_sizes[2] / 2;
    if (n_edges > E_MAX) n_edges = E_MAX;

    int prep_blocks = (n_atoms + 255) / 256;
    prep_kernel<<<prep_blocks, 256>>>(R, Z, a_exp, n_atoms);

    int n_thread_units = (n_edges + 3) / 4;
    int p1_blocks = (n_thread_units + 255) / 256;
    pass1_kernel<<<p1_blocks, 256>>>(idx, n_edges, n_atoms);

    pass2_kernel<<<296, 256>>>(a_num, coef, expo);

    finalize_kernel<<<1, 32>>>(out);
}

// round 3
// speedup vs baseline: 1.4200x; 1.4200x over previous
#include <cuda_runtime.h>
#include <math_constants.h>

// ZBLRepulsion fused: E = sum_edges 0.5*Zi*Zj/dr * f(dist) * cos_cutoff(dr)
// prep: pack {x,y,z,Z} per atom + Z^a_exp LUT. main: gather, filter d2<36,
// inline predicated math (cutoff kills ~98% of edges), block reduce,
// last-block writes output. No compaction, no single-counter atomics.

#define N_ATOMS_MAX 100032
#define EPT 8  // edges per thread

__device__ float4 g_P[N_ATOMS_MAX];   // {x, y, z, Z_as_int_bits}
__device__ float  g_pow[64];          // z^a_exp
__device__ double g_acc;
__device__ int    g_done;

// ---------------------------------------------------------------------------
__global__ void prep_kernel(const float* __restrict__ R,
                            const int* __restrict__ Z,
                            const float* __restrict__ a_exp,
                            int n_atoms) {
    int tid = blockIdx.x * blockDim.x + threadIdx.x;
    if (tid < 64) g_pow[tid] = powf((float)tid, a_exp[0]);
    if (tid == 0) { g_acc = 0.0; g_done = 0; }
    int stride = gridDim.x * blockDim.x;
    for (int i = tid; i < n_atoms; i += stride) {
        float4 p;
        p.x = R[3 * i + 0];
        p.y = R[3 * i + 1];
        p.z = R[3 * i + 2];
        p.w = __int_as_float(Z[i]);
        g_P[i] = p;
    }
}

// ---------------------------------------------------------------------------
__global__ void __launch_bounds__(256)
main_kernel(const int* __restrict__ idx, int n_edges, int n_atoms,
            const float* __restrict__ a_num,
            const float* __restrict__ coef,
            const float* __restrict__ expo,
            float* __restrict__ out) {
    __shared__ float s_pow[64];
    __shared__ float s_red[8];
    __shared__ bool  s_last;
    if (threadIdx.x < 64) s_pow[threadIdx.x] = g_pow[threadIdx.x];
    __syncthreads();

    int t  = blockIdx.x * blockDim.x + threadIdx.x;
    int e0 = t * EPT;

    int is[EPT], js[EPT];
    if (e0 + EPT - 1 < n_edges) {
        // two int4 loads per stream (streaming hint: no reuse, keep L1 for g_P)
        const int4* pi4 = reinterpret_cast<const int4*>(idx + e0);
        const int4* pj4 = reinterpret_cast<const int4*>(idx + n_edges + e0);
        int4 a = __ldcs(pi4 + 0), b = __ldcs(pi4 + 1);
        int4 c = __ldcs(pj4 + 0), d = __ldcs(pj4 + 1);
        is[0]=a.x; is[1]=a.y; is[2]=a.z; is[3]=a.w;
        is[4]=b.x; is[5]=b.y; is[6]=b.z; is[7]=b.w;
        js[0]=c.x; js[1]=c.y; js[2]=c.z; js[3]=c.w;
        js[4]=d.x; js[5]=d.y; js[6]=d.z; js[7]=d.w;
    } else {
#pragma unroll
        for (int k = 0; k < EPT; k++) {
            int e = e0 + k;
            is[k] = (e < n_edges) ? idx[e] : -1;
            js[k] = (e < n_edges) ? idx[n_edges + e] : -1;
        }
    }

    // gather + d2 filter (front-batched loads for MLP)
    float d2v[EPT];
    int   ziv[EPT], zjv[EPT];
    bool  pr[EPT];
#pragma unroll
    for (int k = 0; k < EPT; k++) {
        int i = is[k], j = js[k];
        bool valid = ((unsigned)i < (unsigned)n_atoms) & ((unsigned)j < (unsigned)n_atoms);
        float d2 = 1e30f; int zi = 0, zj = 0;
        if (valid) {
            float4 pi = g_P[i];
            float4 pj = g_P[j];
            float dx = pj.x - pi.x;
            float dy = pj.y - pi.y;
            float dz = pj.z - pi.z;
            d2 = fmaf(dx, dx, fmaf(dy, dy, dz * dz));
            zi = __float_as_int(pi.w);
            zj = __float_as_int(pj.w);
        }
        d2v[k] = d2; ziv[k] = zi; zjv[k] = zj;
        pr[k] = valid && (d2 < 36.0f);   // d2>=36 -> cos_cutoff==0 exactly
    }

    float inv_anum = 1.0f / a_num[0];
    float c0 = coef[0], c1 = coef[1], c2 = coef[2], c3 = coef[3];
    float x0 = expo[0], x1 = expo[1], x2 = expo[2], x3 = expo[3];

    float acc = 0.0f;
#pragma unroll
    for (int k = 0; k < EPT; k++) {
        if (pr[k]) {
            float dr = sqrtf(d2v[k]);
            dr = fmaxf(dr, 0.02f);
            float cut = 0.5f * (__cosf((CUDART_PI_F / 6.0f) * dr) + 1.0f);
            float dist = dr * (s_pow[ziv[k]] + s_pow[zjv[k]]) * inv_anum;
            float f = c0 * __expf(-x0 * dist)
                    + c1 * __expf(-x1 * dist)
                    + c2 * __expf(-x2 * dist)
                    + c3 * __expf(-x3 * dist);
            acc += 0.5f * (float)(ziv[k] * zjv[k]) * f * cut / dr;
        }
    }

    // block reduction
#pragma unroll
    for (int o = 16; o > 0; o >>= 1)
        acc += __shfl_down_sync(0xffffffffu, acc, o);
    int wid = threadIdx.x >> 5;
    if ((threadIdx.x & 31) == 0) s_red[wid] = acc;
    __syncthreads();
    if (threadIdx.x == 0) {
        float v = 0.0f;
#pragma unroll
        for (int w = 0; w < 8; w++) v += s_red[w];
        if (v != 0.0f) atomicAdd(&g_acc, (double)v);
        __threadfence();
        int done = atomicAdd(&g_done, 1);
        s_last = (done == (int)gridDim.x - 1);
    }
    __syncthreads();
    if (s_last && threadIdx.x == 0) {
        // all g_acc contributions are visible (threadfence + done counter)
        double total = *((volatile double*)&g_acc);
        out[0] = (float)total;
    }
}

// ---------------------------------------------------------------------------
extern "C" void kernel_launch(void* const* d_in, const int* in_sizes, int n_in,
                              void* d_out, int out_size) {
    const float* R      = (const float*)d_in[0];
    const int*   Z      = (const int*)d_in[1];
    const int*   idx    = (const int*)d_in[2];
    const float* a_exp  = (const float*)d_in[3];
    const float* a_num  = (const float*)d_in[4];
    const float* coef   = (const float*)d_in[5];
    const float* expo   = (const float*)d_in[6];
    float* out = (float*)d_out;

    int n_atoms = in_sizes[1];
    if (n_atoms > N_ATOMS_MAX) n_atoms = N_ATOMS_MAX;
    int n_edges = in_sizes[2] / 2;

    int prep_blocks = (n_atoms + 255) / 256;
    prep_kernel<<<prep_blocks, 256>>>(R, Z, a_exp, n_atoms);

    int n_threads = (n_edges + EPT - 1) / EPT;
    int blocks = (n_threads + 255) / 256;
    main_kernel<<<blocks, 256>>>(idx, n_edges, n_atoms, a_num, coef, expo, out);
}

// round 6
// speedup vs baseline: 1.5717x; 1.1068x over previous
#include <cuda_runtime.h>
#include <math_constants.h>

// ZBLRepulsion fused: E = sum_edges 0.5*Zi*Zj/dr * f(dist) * cos_cutoff(dr)
// Single gather kernel: d2<36 filter (cos_cutoff==0 beyond), predicated math,
// block reduce, done-counter finalize. <=64 regs -> 4 CTAs/SM.
// d2 clamped to 0.02^2 BEFORE rsqrtf: handles self-edges (d2==0) without NaN
// and implements the reference's lower clip exactly.

#define N_ATOMS_MAX 100032
#define EPT 8  // edges per thread

__device__ float4 g_P[N_ATOMS_MAX];   // {x, y, z, Z_as_int_bits}
__device__ float  g_pow[64];          // z^a_exp
__device__ double g_acc;
__device__ int    g_done;

// ---------------------------------------------------------------------------
__global__ void prep_kernel(const float* __restrict__ R,
                            const int* __restrict__ Z,
                            const float* __restrict__ a_exp,
                            int n_atoms) {
    int tid = blockIdx.x * blockDim.x + threadIdx.x;
    if (tid < 64) g_pow[tid] = powf((float)tid, a_exp[0]);
    if (tid == 0) { g_acc = 0.0; g_done = 0; }
    int stride = gridDim.x * blockDim.x;
    for (int i = tid; i < n_atoms; i += stride) {
        float4 p;
        p.x = R[3 * i + 0];
        p.y = R[3 * i + 1];
        p.z = R[3 * i + 2];
        p.w = __int_as_float(Z[i]);
        g_P[i] = p;
    }
}

// ---------------------------------------------------------------------------
__global__ void __launch_bounds__(256, 4)
main_kernel(const int* __restrict__ idx, int n_edges, int n_atoms,
            const float* __restrict__ a_num,
            const float* __restrict__ coef,
            const float* __restrict__ expo,
            float* __restrict__ out) {
    __shared__ float s_pow[64];
    __shared__ float s_red[8];
    __shared__ bool  s_last;
    if (threadIdx.x < 64) s_pow[threadIdx.x] = g_pow[threadIdx.x];
    __syncthreads();

    int t  = blockIdx.x * blockDim.x + threadIdx.x;
    int e0 = t * EPT;

    int is[EPT], js[EPT];
    if (e0 + EPT - 1 < n_edges) {
        const int4* pi4 = reinterpret_cast<const int4*>(idx + e0);
        const int4* pj4 = reinterpret_cast<const int4*>(idx + n_edges + e0);
        int4 a = __ldcs(pi4 + 0), b = __ldcs(pi4 + 1);
        int4 c = __ldcs(pj4 + 0), d = __ldcs(pj4 + 1);
        is[0]=a.x; is[1]=a.y; is[2]=a.z; is[3]=a.w;
        is[4]=b.x; is[5]=b.y; is[6]=b.z; is[7]=b.w;
        js[0]=c.x; js[1]=c.y; js[2]=c.z; js[3]=c.w;
        js[4]=d.x; js[5]=d.y; js[6]=d.z; js[7]=d.w;
    } else {
#pragma unroll
        for (int k = 0; k < EPT; k++) {
            int e = e0 + k;
            is[k] = (e < n_edges) ? idx[e] : -1;
            js[k] = (e < n_edges) ? idx[n_edges + e] : -1;
        }
    }

    // gather + d2; pack zi|zj<<8 to keep live state small (reg pressure)
    float d2v[EPT];
    int   zzv[EPT];
#pragma unroll
    for (int k = 0; k < EPT; k++) {
        int i = is[k], j = js[k];
        bool valid = ((unsigned)i < (unsigned)n_atoms) & ((unsigned)j < (unsigned)n_atoms);
        float d2 = 1e30f; int zz = 0;
        if (valid) {
            float4 pi = g_P[i];
            float4 pj = g_P[j];
            float dx = pj.x - pi.x;
            float dy = pj.y - pi.y;
            float dz = pj.z - pi.z;
            d2 = fmaf(dx, dx, fmaf(dy, dy, dz * dz));
            zz = __float_as_int(pi.w) | (__float_as_int(pj.w) << 8);
        }
        d2v[k] = d2; zzv[k] = zz;
    }

    float inv_anum = 1.0f / a_num[0];
    float c0 = coef[0], c1 = coef[1], c2 = coef[2], c3 = coef[3];
    float x0 = expo[0], x1 = expo[1], x2 = expo[2], x3 = expo[3];

    float acc = 0.0f;
#pragma unroll
    for (int k = 0; k < EPT; k++) {
        float d2 = d2v[k];
        if (d2 < 36.0f) {                       // beyond: cos_cutoff == 0 exactly
            int zi = zzv[k] & 0xff;
            int zj = (zzv[k] >> 8) & 0xff;
            d2 = fmaxf(d2, 4e-4f);              // lower clip dr>=0.02 (in d2 domain; kills rsqrt(0) NaN)
            float inv_dr = rsqrtf(d2);
            float dr = d2 * inv_dr;             // == sqrt(d2), in [0.02, 6)
            float cut = 0.5f * (__cosf((CUDART_PI_F / 6.0f) * dr) + 1.0f);
            float dist = dr * (s_pow[zi] + s_pow[zj]) * inv_anum;
            float f = c0 * __expf(-x0 * dist)
                    + c1 * __expf(-x1 * dist)
                    + c2 * __expf(-x2 * dist)
                    + c3 * __expf(-x3 * dist);
            acc += 0.5f * (float)(zi * zj) * f * cut * inv_dr;
        }
    }

    // block reduction
#pragma unroll
    for (int o = 16; o > 0; o >>= 1)
        acc += __shfl_down_sync(0xffffffffu, acc, o);
    int wid = threadIdx.x >> 5;
    if ((threadIdx.x & 31) == 0) s_red[wid] = acc;
    __syncthreads();
    if (threadIdx.x == 0) {
        float v = 0.0f;
#pragma unroll
        for (int w = 0; w < 8; w++) v += s_red[w];
        if (v != 0.0f) atomicAdd(&g_acc, (double)v);
        __threadfence();
        int done = atomicAdd(&g_done, 1);
        s_last = (done == (int)gridDim.x - 1);
    }
    __syncthreads();
    if (s_last && threadIdx.x == 0) {
        double total = *((volatile double*)&g_acc);
        out[0] = (float)total;
    }
}

// ---------------------------------------------------------------------------
extern "C" void kernel_launch(void* const* d_in, const int* in_sizes, int n_in,
                              void* d_out, int out_size) {
    const float* R      = (const float*)d_in[0];
    const int*   Z      = (const int*)d_in[1];
    const int*   idx    = (const int*)d_in[2];
    const float* a_exp  = (const float*)d_in[3];
    const float* a_num  = (const float*)d_in[4];
    const float* coef   = (const float*)d_in[5];
    const float* expo   = (const float*)d_in[6];
    float* out = (float*)d_out;

    int n_atoms = in_sizes[1];
    if (n_atoms > N_ATOMS_MAX) n_atoms = N_ATOMS_MAX;
    int n_edges = in_sizes[2] / 2;

    int prep_blocks = (n_atoms + 255) / 256;
    prep_kernel<<<prep_blocks, 256>>>(R, Z, a_exp, n_atoms);

    int n_threads = (n_edges + EPT - 1) / EPT;
    int blocks = (n_threads + 255) / 256;
    main_kernel<<<blocks, 256>>>(idx, n_edges, n_atoms, a_num, coef, expo, out);
}